// round 14
// baseline (speedup 1.0000x reference)
#include <cuda_runtime.h>
#include <cstdint>

#define T_STEPS 100
#define BATCH   256
#define IN_DIM  1024
#define HID     2048
#define OUT_DIM 10
#define BH      (BATCH * HID)
#define TBROWS  (T_STEPS * BATCH)
#define XL_MAX  512

// ---------------- scratch (device globals; no runtime allocation) ----------------
__device__ __align__(128) int8_t   g_X[(size_t)TBROWS * IN_DIM];
__device__ __align__(128) uint16_t g_xlist[(size_t)TBROWS * XL_MAX];   // ascending per row
__device__ __align__(128) int      g_xbnd[TBROWS * 5];                 // 256-chunk starts + len
__device__ __align__(128) float    g_I0p[4ull * TBROWS * HID];         // layer-0 chunk partials [c][row][n]
__device__ __align__(128) float    g_hp[4ull * BATCH * HID];           // hidden chunk partials [c][b][n]
__device__ __align__(128) float    g_v0[BH];
__device__ __align__(128) float    g_v1[BH];
__device__ __align__(128) float    g_vout[BATCH * OUT_DIM];
__device__ __align__(128) float    g_cnt[BATCH * OUT_DIM];
__device__ __align__(128) uint16_t g_s0list[BATCH * HID];              // ascending per b
__device__ __align__(128) int      g_s0bnd[BATCH * 5];                 // 512-chunk starts + len

// ---------------- prep ----------------
__global__ void prep_x_k(const float* __restrict__ in0) {
    __shared__ float tile[32][33];
    const int b  = blockIdx.z;
    const int i0 = blockIdx.x * 32;
    const int t0 = blockIdx.y * 32;
    const int tx = threadIdx.x, ty = threadIdx.y;
    if (t0 + tx < T_STEPS)
        tile[ty][tx] = in0[((size_t)b * IN_DIM + (i0 + ty)) * T_STEPS + t0 + tx];
    __syncthreads();
    const int t = t0 + ty;
    if (t < T_STEPS)
        g_X[((size_t)t * BATCH + b) * IN_DIM + i0 + tx] = (tile[tx][ty] > 0.5f) ? 1 : 0;
}

__global__ void build_xlist_k() {
    const int row  = blockIdx.x * (blockDim.x >> 5) + (threadIdx.x >> 5);
    const int lane = threadIdx.x & 31;
    if (row >= TBROWS) return;
    const int8_t* x = g_X + (size_t)row * IN_DIM;
    uint16_t* lst = g_xlist + (size_t)row * XL_MAX;
    int base = 0;
    if (lane == 0) g_xbnd[row * 5 + 0] = 0;
    for (int c = 0; c < IN_DIM / 32; c++) {
        if ((c & 7) == 0 && c > 0 && lane == 0)
            g_xbnd[row * 5 + (c >> 3)] = base < XL_MAX ? base : XL_MAX;
        const int k = c * 32 + lane;
        const bool sp = x[k] != 0;
        const unsigned m = __ballot_sync(0xffffffffu, sp);
        const int pos = __popc(m & ((1u << lane) - 1u));
        if (sp && base + pos < XL_MAX) lst[base + pos] = (uint16_t)k;
        base += __popc(m);
    }
    if (lane == 0) g_xbnd[row * 5 + 4] = base < XL_MAX ? base : XL_MAX;
}

__global__ void init_k() {
    const int i = blockIdx.x * blockDim.x + threadIdx.x;
    if (i < BH) { g_v0[i] = 0.f; g_v1[i] = 0.f; }
    if (i < BATCH * OUT_DIM) g_vout[i] = 0.f;
}

// serial chunk accumulate over [s,e) of lst, 4x unrolled (order preserved), cols n..n+3
__device__ __forceinline__ float4 chunk_acc(const float* __restrict__ W,
                                            const uint16_t* __restrict__ lst,
                                            int s, int e, int n) {
    float s0 = 0.f, s1 = 0.f, s2 = 0.f, s3 = 0.f;
    int i = s;
    for (; i + 4 <= e; i += 4) {
        const int k0 = lst[i], k1 = lst[i + 1], k2 = lst[i + 2], k3 = lst[i + 3];
        const float4 w0 = *(const float4*)(W + (size_t)k0 * HID + n);
        const float4 w1 = *(const float4*)(W + (size_t)k1 * HID + n);
        const float4 w2 = *(const float4*)(W + (size_t)k2 * HID + n);
        const float4 w3 = *(const float4*)(W + (size_t)k3 * HID + n);
        s0 = __fadd_rn(s0, w0.x); s1 = __fadd_rn(s1, w0.y); s2 = __fadd_rn(s2, w0.z); s3 = __fadd_rn(s3, w0.w);
        s0 = __fadd_rn(s0, w1.x); s1 = __fadd_rn(s1, w1.y); s2 = __fadd_rn(s2, w1.z); s3 = __fadd_rn(s3, w1.w);
        s0 = __fadd_rn(s0, w2.x); s1 = __fadd_rn(s1, w2.y); s2 = __fadd_rn(s2, w2.z); s3 = __fadd_rn(s3, w2.w);
        s0 = __fadd_rn(s0, w3.x); s1 = __fadd_rn(s1, w3.y); s2 = __fadd_rn(s2, w3.z); s3 = __fadd_rn(s3, w3.w);
    }
    for (; i < e; i++) {
        const float4 w = *(const float4*)(W + (size_t)lst[i] * HID + n);
        s0 = __fadd_rn(s0, w.x); s1 = __fadd_rn(s1, w.y); s2 = __fadd_rn(s2, w.z); s3 = __fadd_rn(s3, w.w);
    }
    return make_float4(s0, s1, s2, s3);
}

// ---------------- phase A: per-chunk serial partials ----------------
// CTA = (32 n-cols, chunk c, 256 rows). W slice = 256k x 128B = 32KB, L1-resident.
__global__ void __launch_bounds__(256) phaseA_k(const float* __restrict__ W) {
    const int q  = threadIdx.x & 7;
    const int rg = threadIdx.x >> 3;
    const int n = blockIdx.x * 32 + q * 4;
    const int c = blockIdx.y;
    const int row0 = blockIdx.z * 256 + rg * 8;
    float* __restrict__ out = g_I0p + (size_t)c * TBROWS * HID;
#pragma unroll 1
    for (int j = 0; j < 8; j++) {
        const int row = row0 + j;
        const uint16_t* __restrict__ lst = g_xlist + (size_t)row * XL_MAX;
        const float4 r = chunk_acc(W, lst, g_xbnd[row * 5 + c], g_xbnd[row * 5 + c + 1], n);
        *(float4*)(out + (size_t)row * HID + n) = r;
    }
}

// ---------------- per-step hidden: per-chunk serial partials ----------------
// CTA = (32 n-cols, chunk c, b-half). W slice = 512k x 128B = 64KB, L1-resident. Grid (64,4,2)=512.
__global__ void __launch_bounds__(256) hidden_k(const float* __restrict__ W) {
    const int q  = threadIdx.x & 7;
    const int bg = threadIdx.x >> 3;       // 32 b-groups
    const int n = blockIdx.x * 32 + q * 4;
    const int c = blockIdx.y;
    const int b0 = blockIdx.z * 128 + bg * 4;
    float* __restrict__ out = g_hp + (size_t)c * BH;
#pragma unroll 1
    for (int j = 0; j < 4; j++) {
        const int b = b0 + j;
        const uint16_t* __restrict__ lst = g_s0list + b * HID;
        const float4 r = chunk_acc(W, lst, g_s0bnd[b * 5 + c], g_s0bnd[b * 5 + c + 1], n);
        *(float4*)(out + (size_t)b * HID + n) = r;
    }
}

// ---------------- LIF layer0 + ascending list + chunk bounds (device fn; CTA per b) ----------------
__device__ __forceinline__ void liflist0_body(int t, int b) {
    __shared__ uint8_t fl[HID];
    __shared__ int wpre[9];
    const size_t rowoff = ((size_t)t * BATCH + b) * HID;
    float* vb = g_v0 + (size_t)b * HID;
    const int tid = threadIdx.x;
#pragma unroll
    for (int j = 0; j < 8; j++) {
        const int n = j * 256 + tid;
        const float p0 = g_I0p[rowoff + n];
        const float p1 = g_I0p[(size_t)TBROWS * HID + rowoff + n];
        const float p2 = g_I0p[2ull * TBROWS * HID + rowoff + n];
        const float p3 = g_I0p[3ull * TBROWS * HID + rowoff + n];
        const float cur = __fadd_rn(__fadd_rn(__fadd_rn(p0, p1), p2), p3);
        const float vv = __fadd_rn(__fmul_rn(vb[n], 0.9f), cur);
        const bool sp = vv >= 1.0f;
        vb[n] = sp ? 0.f : vv;
        fl[n] = sp ? 1 : 0;
    }
    __syncthreads();
    const int wid = tid >> 5, lane = tid & 31;
    int cnt = 0;
#pragma unroll
    for (int c = 0; c < 8; c++)
        cnt += __popc(__ballot_sync(0xffffffffu, fl[wid * 256 + c * 32 + lane] != 0));
    if (lane == 0) wpre[wid] = cnt;
    __syncthreads();
    if (tid == 0) {
        int s = 0;
#pragma unroll
        for (int w = 0; w < 8; w++) { const int c = wpre[w]; wpre[w] = s; s += c; }
        wpre[8] = s;
#pragma unroll
        for (int c = 0; c < 4; c++) g_s0bnd[b * 5 + c] = wpre[2 * c];
        g_s0bnd[b * 5 + 4] = s;
    }
    __syncthreads();
    int base = wpre[wid];
#pragma unroll
    for (int c = 0; c < 8; c++) {
        const int n = wid * 256 + c * 32 + lane;
        const bool sp = fl[n] != 0;
        const unsigned m = __ballot_sync(0xffffffffu, sp);
        const int pos = __popc(m & ((1u << lane) - 1u));
        if (sp) g_s0list[b * HID + base + pos] = (uint16_t)n;
        base += __popc(m);
    }
}

__global__ void __launch_bounds__(256) liflist0_k(int t) {
    liflist0_body(t, blockIdx.x);
}

// ---------------- LIF1 + output gather (fp64 exact) + LIF out + rate (device fn) ----------------
__device__ __forceinline__ void lif1out_body(const float* __restrict__ Who, int t,
                                             float* __restrict__ d_out, int b) {
    const int tid = threadIdx.x;
    double acc[OUT_DIM];
#pragma unroll
    for (int q = 0; q < OUT_DIM; q++) acc[q] = 0.0;
#pragma unroll
    for (int j = 0; j < 8; j++) {
        const int n = j * 256 + tid;
        const size_t o = (size_t)b * HID + n;
        const float p0 = g_hp[o];
        const float p1 = g_hp[(size_t)BH + o];
        const float p2 = g_hp[2ull * BH + o];
        const float p3 = g_hp[3ull * BH + o];
        const float cur = __fadd_rn(__fadd_rn(__fadd_rn(p0, p1), p2), p3);
        const float vv = __fadd_rn(__fmul_rn(g_v1[o], 0.9f), cur);
        const bool sp = vv >= 1.0f;
        g_v1[o] = sp ? 0.f : vv;
        if (sp) {
#pragma unroll
            for (int q = 0; q < OUT_DIM; q++) acc[q] += (double)__ldg(Who + n * OUT_DIM + q);
        }
    }
    __shared__ double sred[OUT_DIM][8];
#pragma unroll
    for (int off = 16; off > 0; off >>= 1)
#pragma unroll
        for (int q = 0; q < OUT_DIM; q++)
            acc[q] += __shfl_down_sync(0xffffffffu, acc[q], off);
    if ((tid & 31) == 0)
#pragma unroll
        for (int q = 0; q < OUT_DIM; q++) sred[q][tid >> 5] = acc[q];
    __syncthreads();
    if (tid < OUT_DIM) {
        const double curd = ((sred[tid][0] + sred[tid][1]) + (sred[tid][2] + sred[tid][3]))
                          + ((sred[tid][4] + sred[tid][5]) + (sred[tid][6] + sred[tid][7]));
        const int o = b * OUT_DIM + tid;
        const float vo = __fadd_rn(__fmul_rn(g_vout[o], 0.9f), (float)curd);
        const bool sp = vo >= 1.0f;
        g_vout[o] = sp ? 0.f : vo;
        const float c = (t == 0 ? 0.f : g_cnt[o]) + (sp ? 1.f : 0.f);
        if (t == T_STEPS - 1) d_out[o] = c / 100.0f;
        else g_cnt[o] = c;
    }
}

// fused tail: blocks 0-255 do lif1out(t); blocks 256-511 do liflist0(t+1) (independent tasks)
__global__ void __launch_bounds__(256) fuse_k(const float* __restrict__ Who, int t,
                                              float* __restrict__ d_out) {
    if (blockIdx.x < BATCH) lif1out_body(Who, t, d_out, blockIdx.x);
    else if (t + 1 < T_STEPS) liflist0_body(t + 1, blockIdx.x - BATCH);
}

// ---------------- launch ----------------
extern "C" void kernel_launch(void* const* d_in, const int* in_sizes, int n_in,
                              void* d_out, int out_size) {
    (void)in_sizes; (void)n_in; (void)out_size;
    const float* in_bins = (const float*)d_in[0];
    const float* W_ih    = (const float*)d_in[1];
    const float* W_hh    = (const float*)d_in[2];
    const float* W_ho    = (const float*)d_in[3];
    float* out = (float*)d_out;

    init_k<<<2048, 256>>>();
    prep_x_k<<<dim3(IN_DIM / 32, 4, BATCH), dim3(32, 32)>>>(in_bins);
    build_xlist_k<<<(TBROWS + 7) / 8, 256>>>();

    phaseA_k<<<dim3(HID / 32, 4, TBROWS / 256), 256>>>(W_ih);

    liflist0_k<<<BATCH, 256>>>(0);
    for (int t = 0; t < T_STEPS; t++) {
        hidden_k<<<dim3(HID / 32, 4, 2), 256>>>(W_hh);
        fuse_k<<<BATCH * 2, 256>>>(W_ho, t, out);
    }
}

// round 15
// speedup vs baseline: 1.0148x; 1.0148x over previous
#include <cuda_runtime.h>
#include <cstdint>

#define T_STEPS 100
#define BATCH   256
#define IN_DIM  1024
#define HID     2048
#define OUT_DIM 10
#define BH      (BATCH * HID)
#define TBROWS  (T_STEPS * BATCH)
#define XL_MAX  512

// ---------------- scratch (device globals; no runtime allocation) ----------------
__device__ __align__(128) int8_t   g_X[(size_t)TBROWS * IN_DIM];
__device__ __align__(128) uint16_t g_xlist[(size_t)TBROWS * XL_MAX];   // ascending per row
__device__ __align__(128) int      g_xbnd[TBROWS * 5];                 // 256-chunk starts + len
__device__ __align__(128) float    g_I0p[4ull * TBROWS * HID];         // layer-0 chunk partials [c][row][n]
__device__ __align__(128) float    g_hp[4ull * BATCH * HID];           // hidden chunk partials [c][b][n]
__device__ __align__(128) float    g_v0[BH];
__device__ __align__(128) float    g_v1[BH];
__device__ __align__(128) float    g_vout[BATCH * OUT_DIM];
__device__ __align__(128) float    g_cnt[BATCH * OUT_DIM];
__device__ __align__(128) uint16_t g_s0list[BATCH * HID];              // ascending per b
__device__ __align__(128) int      g_s0bnd[BATCH * 5];                 // 512-chunk starts + len

// ---------------- prep ----------------
__global__ void prep_x_k(const float* __restrict__ in0) {
    __shared__ float tile[32][33];
    const int b  = blockIdx.z;
    const int i0 = blockIdx.x * 32;
    const int t0 = blockIdx.y * 32;
    const int tx = threadIdx.x, ty = threadIdx.y;
    if (t0 + tx < T_STEPS)
        tile[ty][tx] = in0[((size_t)b * IN_DIM + (i0 + ty)) * T_STEPS + t0 + tx];
    __syncthreads();
    const int t = t0 + ty;
    if (t < T_STEPS)
        g_X[((size_t)t * BATCH + b) * IN_DIM + i0 + tx] = (tile[tx][ty] > 0.5f) ? 1 : 0;
}

__global__ void build_xlist_k() {
    const int row  = blockIdx.x * (blockDim.x >> 5) + (threadIdx.x >> 5);
    const int lane = threadIdx.x & 31;
    if (row >= TBROWS) return;
    const int8_t* x = g_X + (size_t)row * IN_DIM;
    uint16_t* lst = g_xlist + (size_t)row * XL_MAX;
    int base = 0;
    if (lane == 0) g_xbnd[row * 5 + 0] = 0;
    for (int c = 0; c < IN_DIM / 32; c++) {
        if ((c & 7) == 0 && c > 0 && lane == 0)
            g_xbnd[row * 5 + (c >> 3)] = base < XL_MAX ? base : XL_MAX;
        const int k = c * 32 + lane;
        const bool sp = x[k] != 0;
        const unsigned m = __ballot_sync(0xffffffffu, sp);
        const int pos = __popc(m & ((1u << lane) - 1u));
        if (sp && base + pos < XL_MAX) lst[base + pos] = (uint16_t)k;
        base += __popc(m);
    }
    if (lane == 0) g_xbnd[row * 5 + 4] = base < XL_MAX ? base : XL_MAX;
}

__global__ void init_k() {
    const int i = blockIdx.x * blockDim.x + threadIdx.x;
    if (i < BH) { g_v0[i] = 0.f; g_v1[i] = 0.f; }
    if (i < BATCH * OUT_DIM) g_vout[i] = 0.f;
}

// ---------------- software-pipelined serial chunk accumulate ----------------
// Adds applied strictly in ascending i (bit-exact LTR chain); loads scheduled 1 block ahead.
__device__ __forceinline__ float4 chunk_acc(const float* __restrict__ W,
                                            const uint16_t* __restrict__ lst,
                                            int s, int e, int n) {
    float s0 = 0.f, s1 = 0.f, s2 = 0.f, s3 = 0.f;
    int i = s;
    if (e - i >= 8) {
        // prologue: block A
        int ka0 = lst[i], ka1 = lst[i + 1], ka2 = lst[i + 2], ka3 = lst[i + 3];
        float4 a0 = *(const float4*)(W + (size_t)ka0 * HID + n);
        float4 a1 = *(const float4*)(W + (size_t)ka1 * HID + n);
        float4 a2 = *(const float4*)(W + (size_t)ka2 * HID + n);
        float4 a3 = *(const float4*)(W + (size_t)ka3 * HID + n);
        int ip = i + 4;
#pragma unroll 1
        for (; ip + 4 <= e; ip += 4) {
            // load block B (hidden behind block-A FADDs)
            const int kb0 = lst[ip], kb1 = lst[ip + 1], kb2 = lst[ip + 2], kb3 = lst[ip + 3];
            const float4 b0 = *(const float4*)(W + (size_t)kb0 * HID + n);
            const float4 b1 = *(const float4*)(W + (size_t)kb1 * HID + n);
            const float4 b2 = *(const float4*)(W + (size_t)kb2 * HID + n);
            const float4 b3 = *(const float4*)(W + (size_t)kb3 * HID + n);
            // accumulate block A in order
            s0 = __fadd_rn(s0, a0.x); s1 = __fadd_rn(s1, a0.y); s2 = __fadd_rn(s2, a0.z); s3 = __fadd_rn(s3, a0.w);
            s0 = __fadd_rn(s0, a1.x); s1 = __fadd_rn(s1, a1.y); s2 = __fadd_rn(s2, a1.z); s3 = __fadd_rn(s3, a1.w);
            s0 = __fadd_rn(s0, a2.x); s1 = __fadd_rn(s1, a2.y); s2 = __fadd_rn(s2, a2.z); s3 = __fadd_rn(s3, a2.w);
            s0 = __fadd_rn(s0, a3.x); s1 = __fadd_rn(s1, a3.y); s2 = __fadd_rn(s2, a3.z); s3 = __fadd_rn(s3, a3.w);
            a0 = b0; a1 = b1; a2 = b2; a3 = b3;
        }
        // drain block A
        s0 = __fadd_rn(s0, a0.x); s1 = __fadd_rn(s1, a0.y); s2 = __fadd_rn(s2, a0.z); s3 = __fadd_rn(s3, a0.w);
        s0 = __fadd_rn(s0, a1.x); s1 = __fadd_rn(s1, a1.y); s2 = __fadd_rn(s2, a1.z); s3 = __fadd_rn(s3, a1.w);
        s0 = __fadd_rn(s0, a2.x); s1 = __fadd_rn(s1, a2.y); s2 = __fadd_rn(s2, a2.z); s3 = __fadd_rn(s3, a2.w);
        s0 = __fadd_rn(s0, a3.x); s1 = __fadd_rn(s1, a3.y); s2 = __fadd_rn(s2, a3.z); s3 = __fadd_rn(s3, a3.w);
        i = ip;
    }
    for (; i < e; i++) {
        const float4 w = *(const float4*)(W + (size_t)lst[i] * HID + n);
        s0 = __fadd_rn(s0, w.x); s1 = __fadd_rn(s1, w.y); s2 = __fadd_rn(s2, w.z); s3 = __fadd_rn(s3, w.w);
    }
    return make_float4(s0, s1, s2, s3);
}

// ---------------- phase A: per-chunk serial partials ----------------
// CTA = (32 n-cols, chunk c, 256 rows). W slice = 256k x 128B = 32KB, L1-resident.
__global__ void __launch_bounds__(256) phaseA_k(const float* __restrict__ W) {
    const int q  = threadIdx.x & 7;
    const int rg = threadIdx.x >> 3;
    const int n = blockIdx.x * 32 + q * 4;
    const int c = blockIdx.y;
    const int row0 = blockIdx.z * 256 + rg * 8;
    float* __restrict__ out = g_I0p + (size_t)c * TBROWS * HID;
#pragma unroll 1
    for (int j = 0; j < 8; j++) {
        const int row = row0 + j;
        const uint16_t* __restrict__ lst = g_xlist + (size_t)row * XL_MAX;
        const float4 r = chunk_acc(W, lst, g_xbnd[row * 5 + c], g_xbnd[row * 5 + c + 1], n);
        *(float4*)(out + (size_t)row * HID + n) = r;
    }
}

// ---------------- per-step hidden: per-chunk serial partials ----------------
// CTA = (32 n-cols, chunk c, b-half). W slice = 512k x 128B = 64KB, L1-resident. Grid (64,4,2).
__global__ void __launch_bounds__(256) hidden_k(const float* __restrict__ W) {
    const int q  = threadIdx.x & 7;
    const int bg = threadIdx.x >> 3;       // 32 b-groups
    const int n = blockIdx.x * 32 + q * 4;
    const int c = blockIdx.y;
    const int b0 = blockIdx.z * 128 + bg * 4;
    float* __restrict__ out = g_hp + (size_t)c * BH;
#pragma unroll 1
    for (int j = 0; j < 4; j++) {
        const int b = b0 + j;
        const uint16_t* __restrict__ lst = g_s0list + b * HID;
        const float4 r = chunk_acc(W, lst, g_s0bnd[b * 5 + c], g_s0bnd[b * 5 + c + 1], n);
        *(float4*)(out + (size_t)b * HID + n) = r;
    }
}

// ---------------- LIF layer0 + ascending list + chunk bounds (device fn; CTA per b) ----------------
__device__ __forceinline__ void liflist0_body(int t, int b) {
    __shared__ uint8_t fl[HID];
    __shared__ int wpre[9];
    const size_t rowoff = ((size_t)t * BATCH + b) * HID;
    float* vb = g_v0 + (size_t)b * HID;
    const int tid = threadIdx.x;
#pragma unroll
    for (int j = 0; j < 8; j++) {
        const int n = j * 256 + tid;
        const float p0 = g_I0p[rowoff + n];
        const float p1 = g_I0p[(size_t)TBROWS * HID + rowoff + n];
        const float p2 = g_I0p[2ull * TBROWS * HID + rowoff + n];
        const float p3 = g_I0p[3ull * TBROWS * HID + rowoff + n];
        const float cur = __fadd_rn(__fadd_rn(__fadd_rn(p0, p1), p2), p3);
        const float vv = __fadd_rn(__fmul_rn(vb[n], 0.9f), cur);
        const bool sp = vv >= 1.0f;
        vb[n] = sp ? 0.f : vv;
        fl[n] = sp ? 1 : 0;
    }
    __syncthreads();
    const int wid = tid >> 5, lane = tid & 31;
    int cnt = 0;
#pragma unroll
    for (int c = 0; c < 8; c++)
        cnt += __popc(__ballot_sync(0xffffffffu, fl[wid * 256 + c * 32 + lane] != 0));
    if (lane == 0) wpre[wid] = cnt;
    __syncthreads();
    if (tid == 0) {
        int s = 0;
#pragma unroll
        for (int w = 0; w < 8; w++) { const int c = wpre[w]; wpre[w] = s; s += c; }
        wpre[8] = s;
#pragma unroll
        for (int c = 0; c < 4; c++) g_s0bnd[b * 5 + c] = wpre[2 * c];
        g_s0bnd[b * 5 + 4] = s;
    }
    __syncthreads();
    int base = wpre[wid];
#pragma unroll
    for (int c = 0; c < 8; c++) {
        const int n = wid * 256 + c * 32 + lane;
        const bool sp = fl[n] != 0;
        const unsigned m = __ballot_sync(0xffffffffu, sp);
        const int pos = __popc(m & ((1u << lane) - 1u));
        if (sp) g_s0list[b * HID + base + pos] = (uint16_t)n;
        base += __popc(m);
    }
}

__global__ void __launch_bounds__(256) liflist0_k(int t) {
    liflist0_body(t, blockIdx.x);
}

// ---------------- LIF1 + output gather (fp64 exact) + LIF out + rate (device fn) ----------------
__device__ __forceinline__ void lif1out_body(const float* __restrict__ Who, int t,
                                             float* __restrict__ d_out, int b) {
    const int tid = threadIdx.x;
    double acc[OUT_DIM];
#pragma unroll
    for (int q = 0; q < OUT_DIM; q++) acc[q] = 0.0;
#pragma unroll
    for (int j = 0; j < 8; j++) {
        const int n = j * 256 + tid;
        const size_t o = (size_t)b * HID + n;
        const float p0 = g_hp[o];
        const float p1 = g_hp[(size_t)BH + o];
        const float p2 = g_hp[2ull * BH + o];
        const float p3 = g_hp[3ull * BH + o];
        const float cur = __fadd_rn(__fadd_rn(__fadd_rn(p0, p1), p2), p3);
        const float vv = __fadd_rn(__fmul_rn(g_v1[o], 0.9f), cur);
        const bool sp = vv >= 1.0f;
        g_v1[o] = sp ? 0.f : vv;
        if (sp) {
#pragma unroll
            for (int q = 0; q < OUT_DIM; q++) acc[q] += (double)__ldg(Who + n * OUT_DIM + q);
        }
    }
    __shared__ double sred[OUT_DIM][8];
#pragma unroll
    for (int off = 16; off > 0; off >>= 1)
#pragma unroll
        for (int q = 0; q < OUT_DIM; q++)
            acc[q] += __shfl_down_sync(0xffffffffu, acc[q], off);
    if ((tid & 31) == 0)
#pragma unroll
        for (int q = 0; q < OUT_DIM; q++) sred[q][tid >> 5] = acc[q];
    __syncthreads();
    if (tid < OUT_DIM) {
        const double curd = ((sred[tid][0] + sred[tid][1]) + (sred[tid][2] + sred[tid][3]))
                          + ((sred[tid][4] + sred[tid][5]) + (sred[tid][6] + sred[tid][7]));
        const int o = b * OUT_DIM + tid;
        const float vo = __fadd_rn(__fmul_rn(g_vout[o], 0.9f), (float)curd);
        const bool sp = vo >= 1.0f;
        g_vout[o] = sp ? 0.f : vo;
        const float c = (t == 0 ? 0.f : g_cnt[o]) + (sp ? 1.f : 0.f);
        if (t == T_STEPS - 1) d_out[o] = c / 100.0f;
        else g_cnt[o] = c;
    }
}

// fused tail: blocks 0-255 do lif1out(t); blocks 256-511 do liflist0(t+1) (independent tasks)
__global__ void __launch_bounds__(256) fuse_k(const float* __restrict__ Who, int t,
                                              float* __restrict__ d_out) {
    if (blockIdx.x < BATCH) lif1out_body(Who, t, d_out, blockIdx.x);
    else if (t + 1 < T_STEPS) liflist0_body(t + 1, blockIdx.x - BATCH);
}

// ---------------- launch ----------------
extern "C" void kernel_launch(void* const* d_in, const int* in_sizes, int n_in,
                              void* d_out, int out_size) {
    (void)in_sizes; (void)n_in; (void)out_size;
    const float* in_bins = (const float*)d_in[0];
    const float* W_ih    = (const float*)d_in[1];
    const float* W_hh    = (const float*)d_in[2];
    const float* W_ho    = (const float*)d_in[3];
    float* out = (float*)d_out;

    init_k<<<2048, 256>>>();
    prep_x_k<<<dim3(IN_DIM / 32, 4, BATCH), dim3(32, 32)>>>(in_bins);
    build_xlist_k<<<(TBROWS + 7) / 8, 256>>>();

    phaseA_k<<<dim3(HID / 32, 4, TBROWS / 256), 256>>>(W_ih);

    liflist0_k<<<BATCH, 256>>>(0);
    for (int t = 0; t < T_STEPS; t++) {
        hidden_k<<<dim3(HID / 32, 4, 2), 256>>>(W_hh);
        fuse_k<<<BATCH * 2, 256>>>(W_ho, t, out);
    }
}